// round 6
// baseline (speedup 1.0000x reference)
#include <cuda_runtime.h>
#include <cstdint>
#include <cstddef>

#define NB     32
#define NLAT   721
#define NLON   1440
#define NVEC   360          // NLON / 4
#define NWORDS 45           // NLON / 32
#define NTH    128
#define NROWS  (NB * NLAT)  // 23072

// Extended row: [0,1440) and duplicate [1440,2880), with 16B-granular skew
// phys(j) = j + 4*(j>>5). Max phys = 2879 + 4*89 = 3235 -> pad to 3240.
#define EXTSZ  3240
#define EIDX(j) ((j) + (((j) >> 3) & ~3))

// Cross-CTA scratch (no allocations allowed).
__device__ int g_row_valid[NROWS];
__device__ int g_ticket = 0;

__device__ __forceinline__ bool nan_f(float x) {
    return (__float_as_uint(x) & 0x7FFFFFFFu) > 0x7F800000u;
}

// Butterfly-combine 4-bit validity nibbles across groups of 8 lanes into a
// 32-bit mask word (bit 4k+j = validity of element 4*(group_base+k)+j).
__device__ __forceinline__ unsigned combine8(unsigned v, int lane) {
    unsigned o = __shfl_xor_sync(0xFFFFFFFFu, v, 1);
    v = (lane & 1) ? ((v << 4) | o) : ((o << 4) | v);
    o = __shfl_xor_sync(0xFFFFFFFFu, v, 2);
    v = (lane & 2) ? ((v << 8) | o) : ((o << 8) | v);
    o = __shfl_xor_sync(0xFFFFFFFFu, v, 4);
    v = (lane & 4) ? ((v << 16) | o) : ((o << 16) | v);
    return v;
}

__device__ __forceinline__ unsigned nib_of(float4 r) {
    return (unsigned)(!nan_f(r.x))        | ((unsigned)(!nan_f(r.y)) << 1)
         | ((unsigned)(!nan_f(r.z)) << 2) | ((unsigned)(!nan_f(r.w)) << 3);
}

// ---------------------------------------------------------------------------
// Single fused kernel: one CTA per (b,lat) row; last CTA does the polar fill.
// ---------------------------------------------------------------------------
__global__ void __launch_bounds__(NTH)
fill_kernel(const float4* __restrict__ sst4, const float* __restrict__ sst,
            float* __restrict__ out)
{
    __shared__ float    sx[EXTSZ];      // skewed extended row
    __shared__ unsigned mask[NWORDS];
    __shared__ int      Ptab[NWORDS];   // prev valid idx strictly before word w
    __shared__ int      Ntab[NWORDS];   // next valid idx strictly after  word w
    __shared__ int      s_is_last;

    const int row  = blockIdx.x;        // b * NLAT + h
    const int t    = threadIdx.x;
    const int lane = t & 31;
    const bool has2 = (t < NVEC - 256); // t < 104

    const float4* __restrict__ src = sst4 + (size_t)row * NVEC;
    float4*       __restrict__ dst = (float4*)(out + (size_t)row * NLON);

    // ---- Front-batched loads (3 independent LDG.128) ----
    float4 r0 = src[t];
    float4 r1 = src[t + 128];
    float4 r2 = make_float4(0.f, 0.f, 0.f, 0.f);
    if (has2) r2 = src[t + 256];

    // ---- Store to skewed extended smem (float4 index: vec + (vec>>3)) ----
    float4* sx4 = (float4*)sx;
    {
        const int v0 = t,            v0b = t + 360;
        const int v1 = t + 128,      v1b = t + 488;
        sx4[v0 + (v0 >> 3)]   = r0;  sx4[v0b + (v0b >> 3)] = r0;
        sx4[v1 + (v1 >> 3)]   = r1;  sx4[v1b + (v1b >> 3)] = r1;
        if (has2) {
            const int v2 = t + 256,  v2b = t + 616;
            sx4[v2 + (v2 >> 3)]   = r2;
            sx4[v2b + (v2b >> 3)] = r2;
        }
    }

    // ---- Validity nibbles (kept) + mask words via shuffles ----
    const unsigned nib0 = nib_of(r0);
    const unsigned nib1 = nib_of(r1);
    const unsigned nib2 = has2 ? nib_of(r2) : 0u;
    unsigned w0 = combine8(nib0, lane);
    unsigned w1 = combine8(nib1, lane);
    unsigned w2 = combine8(nib2, lane);
    if ((lane & 7) == 0) {
        const int widx = t >> 3;        // 0..15
        mask[widx]      = w0;
        mask[widx + 16] = w1;
        if (widx + 32 < NWORDS) mask[widx + 32] = w2;
    }
    __syncthreads();

    // ---- Word-validity bitmap B (redundant per warp: 2 ballots) ----
    const unsigned mwa = (lane < NWORDS)      ? mask[lane]      : 0u;
    const unsigned mwb = (lane + 32 < NWORDS) ? mask[lane + 32] : 0u;
    const unsigned b1 = __ballot_sync(0xFFFFFFFFu, mwa != 0u);
    const unsigned b2 = __ballot_sync(0xFFFFFFFFu, mwb != 0u);
    const unsigned long long B = ((unsigned long long)b2 << 32) | b1;
    const bool rv = (B != 0ull);

    if (t == 0) g_row_valid[row] = rv ? 1 : 0;

    // ---- Per-word prev/next tables (threads 0..44) ----
    if (rv && t < NWORDS) {
        const int fw = __ffsll((long long)B) - 1;
        const int firstv = (fw << 5) + __ffs(mask[fw]) - 1;
        const int lw = 63 - __clzll((long long)B);
        const int lastv  = (lw << 5) + 31 - __clz(mask[lw]);

        const unsigned long long lowB = B & ((1ull << t) - 1ull);
        int pv = lastv - NLON;                          // circular wrap
        if (lowB) {
            const int pw = 63 - __clzll((long long)lowB);
            pv = (pw << 5) + 31 - __clz(mask[pw]);
        }
        Ptab[t] = pv;

        const unsigned long long highB = B >> (t + 1);
        int nv = firstv + NLON;                         // circular wrap
        if (highB) {
            const int nw = (t + 1) + __ffsll((long long)highB) - 1;
            nv = (nw << 5) + __ffs(mask[nw]) - 1;
        }
        Ntab[t] = nv;
    }
    __syncthreads();

    // ---- Branch-free interpolation ----
    if (rv) {
        const int bpos0 = (t & 7) << 2;                 // bit offset in word
        const unsigned lomask = (1u << bpos0) - 1u;

        #pragma unroll
        for (int k = 0; k < 3; k++) {
            if (k == 2 && !has2) break;
            const int vec   = t + k * NTH;
            const int i0    = vec << 2;
            const int w     = vec >> 3;
            const int wbase = w << 5;
            const unsigned cur = mask[w];
            const unsigned nib = (k == 0) ? nib0 : (k == 1) ? nib1 : nib2;
            const float4 r = (k == 0) ? r0 : (k == 1) ? r1 : r2;

            // Base prev: largest valid strictly below bpos0 (else Ptab).
            const unsigned lm = cur & lomask;
            const int prevB = lm ? (wbase + 31 - __clz(lm)) : Ptab[w];
            // Base next: smallest valid strictly above bpos0+3 (else Ntab).
            const unsigned long long hm = (unsigned long long)cur >> (bpos0 + 4);
            const int nextB = hm ? (wbase + bpos0 + 4 + __ffsll((long long)hm) - 1)
                                 : Ntab[w];

            // Incremental prev (ascending) / next (descending): 1 SEL each.
            const int p0 = (nib & 1u) ? (i0    ) : prevB;
            const int p1 = (nib & 2u) ? (i0 + 1) : p0;
            const int p2 = (nib & 4u) ? (i0 + 2) : p1;
            const int p3 = (nib & 8u) ? (i0 + 3) : p2;
            const int n3 = (nib & 8u) ? (i0 + 3) : nextB;
            const int n2 = (nib & 4u) ? (i0 + 2) : n3;
            const int n1 = (nib & 2u) ? (i0 + 1) : n2;
            const int n0 = (nib & 1u) ? (i0    ) : n1;

            float res[4];
            const int   P[4]  = {p0, p1, p2, p3};
            const int   N[4]  = {n0, n1, n2, n3};
            const float RC[4] = {r.x, r.y, r.z, r.w};
            #pragma unroll
            for (int c = 0; c < 4; c++) {
                const int pc = P[c], nc = N[c];
                // NaN element: pc < i < nc (dtot >= 2). Valid: discarded below.
                const float tt = __fdividef((float)(i0 + c - pc), (float)(nc - pc));
                const int ja = pc + NLON;               // in [0, 2880)
                const int jb = nc;                      // in [0, 2880)
                const float sp = sx[EIDX(ja)];
                const float sn = sx[EIDX(jb)];
                const float iv = fmaf(tt, sn - sp, sp);
                res[c] = ((nib >> c) & 1u) ? RC[c] : iv;
            }
            dst[vec] = make_float4(res[0], res[1], res[2], res[3]);
        }
    } else {
        dst[t]       = r0;
        dst[t + 128] = r1;
        if (has2) dst[t + 256] = r2;
    }

    // ---- Last-CTA polar fill (ticket pattern; graph-capturable) ----
    __threadfence();
    __syncthreads();
    if (t == 0) {
        const int ticket = atomicAdd(&g_ticket, 1);
        s_is_last = (ticket == (int)gridDim.x - 1) ? 1 : 0;
    }
    __syncthreads();
    if (!s_is_last) return;

    for (int b = 0; b < NB; b++) {
        int lr = NLAT - 1;
        while (lr >= 0 && !g_row_valid[b * NLAT + lr]) lr--;
        if (lr < 0 || lr == NLAT - 1) continue;         // common case

        const float* __restrict__ fill = out + ((size_t)b * NLAT + lr) * NLON;
        for (int h = lr + 1; h < NLAT; h++) {
            const float* __restrict__ sr   = sst + ((size_t)b * NLAT + h) * NLON;
            float*       __restrict__ orow = out + ((size_t)b * NLAT + h) * NLON;
            for (int i = t; i < NLON; i += NTH) {
                if (nan_f(sr[i])) orow[i] = fill[i];
            }
        }
    }
    if (t == 0) g_ticket = 0;                           // reset for next replay
}

// ---------------------------------------------------------------------------
extern "C" void kernel_launch(void* const* d_in, const int* in_sizes, int n_in,
                              void* d_out, int out_size)
{
    const float* sst = (const float*)d_in[0];
    float*       out = (float*)d_out;

    fill_kernel<<<NROWS, NTH>>>((const float4*)sst, sst, out);
}

// round 7
// speedup vs baseline: 1.0478x; 1.0478x over previous
#include <cuda_runtime.h>
#include <cstdint>
#include <cstddef>

#define NB     32
#define NLAT   721
#define NLON   1440
#define NVEC   360          // NLON / 4
#define NWORDS 45           // NLON / 32
#define NTH    128
#define NROWS  (NB * NLAT)  // 23072

// Extended row: [0,1440) + duplicate [1440,2880), 16B-granular skew
// phys(j) = j + 4*(j>>3 & ~3)  (i.e. +4 per 32 floats). Max 3235 -> 3240.
#define EXTSZ  3240
#define EIDX(j) ((j) + (((j) >> 3) & ~3))

// Cross-CTA scratch (no allocations allowed).
__device__ int g_row_valid[NROWS];
__device__ int g_ticket = 0;

__device__ __forceinline__ bool nan_f(float x) {
    return (__float_as_uint(x) & 0x7FFFFFFFu) > 0x7F800000u;
}

__device__ __forceinline__ unsigned combine8(unsigned v, int lane) {
    unsigned o = __shfl_xor_sync(0xFFFFFFFFu, v, 1);
    v = (lane & 1) ? ((v << 4) | o) : ((o << 4) | v);
    o = __shfl_xor_sync(0xFFFFFFFFu, v, 2);
    v = (lane & 2) ? ((v << 8) | o) : ((o << 8) | v);
    o = __shfl_xor_sync(0xFFFFFFFFu, v, 4);
    v = (lane & 4) ? ((v << 16) | o) : ((o << 16) | v);
    return v;
}

__device__ __forceinline__ unsigned nib_of(float4 r) {
    return (unsigned)(!nan_f(r.x))        | ((unsigned)(!nan_f(r.y)) << 1)
         | ((unsigned)(!nan_f(r.z)) << 2) | ((unsigned)(!nan_f(r.w)) << 3);
}

// ---------------------------------------------------------------------------
// Single fused kernel: one CTA per (b,lat) row; last CTA does the polar fill.
// Per nibble of 4 elements: only TWO data LDS (boundary values); all
// in-nibble prev/next values ride 1-SEL-per-element register chains.
// ---------------------------------------------------------------------------
__global__ void __launch_bounds__(NTH)
fill_kernel(const float4* __restrict__ sst4, const float* __restrict__ sst,
            float* __restrict__ out)
{
    __shared__ float    sx[EXTSZ];      // skewed extended row
    __shared__ unsigned mask[NWORDS];
    __shared__ int      Ptab[NWORDS];   // prev valid idx strictly before word w
    __shared__ int      Ntab[NWORDS];   // next valid idx strictly after  word w
    __shared__ int      s_is_last;

    const int row  = blockIdx.x;        // b * NLAT + h
    const int t    = threadIdx.x;
    const int lane = t & 31;
    const bool has2 = (t < NVEC - 256); // t < 104

    const float4* __restrict__ src = sst4 + (size_t)row * NVEC;
    float4*       __restrict__ dst = (float4*)(out + (size_t)row * NLON);

    // ---- Front-batched loads (3 independent LDG.128) ----
    float4 r0 = src[t];
    float4 r1 = src[t + 128];
    float4 r2 = make_float4(0.f, 0.f, 0.f, 0.f);
    if (has2) r2 = src[t + 256];

    // ---- Store to skewed extended smem (float4 idx: vec + (vec>>3)) ----
    float4* sx4 = (float4*)sx;
    {
        const int v0 = t,            v0b = t + 360;
        const int v1 = t + 128,      v1b = t + 488;
        sx4[v0 + (v0 >> 3)]   = r0;  sx4[v0b + (v0b >> 3)] = r0;
        sx4[v1 + (v1 >> 3)]   = r1;  sx4[v1b + (v1b >> 3)] = r1;
        if (has2) {
            const int v2 = t + 256,  v2b = t + 616;
            sx4[v2 + (v2 >> 3)]   = r2;
            sx4[v2b + (v2b >> 3)] = r2;
        }
    }

    // ---- Validity nibbles + mask words via shuffles ----
    const unsigned nib0 = nib_of(r0);
    const unsigned nib1 = nib_of(r1);
    const unsigned nib2 = has2 ? nib_of(r2) : 0u;
    unsigned w0 = combine8(nib0, lane);
    unsigned w1 = combine8(nib1, lane);
    unsigned w2 = combine8(nib2, lane);
    if ((lane & 7) == 0) {
        const int widx = t >> 3;        // 0..15
        mask[widx]      = w0;
        mask[widx + 16] = w1;
        if (widx + 32 < NWORDS) mask[widx + 32] = w2;
    }
    __syncthreads();

    // ---- Word-validity bitmap B (redundant per warp: 2 ballots) ----
    const unsigned mwa = (lane < NWORDS)      ? mask[lane]      : 0u;
    const unsigned mwb = (lane + 32 < NWORDS) ? mask[lane + 32] : 0u;
    const unsigned b1 = __ballot_sync(0xFFFFFFFFu, mwa != 0u);
    const unsigned b2 = __ballot_sync(0xFFFFFFFFu, mwb != 0u);
    const unsigned long long B = ((unsigned long long)b2 << 32) | b1;
    const bool rv = (B != 0ull);

    if (t == 0) g_row_valid[row] = rv ? 1 : 0;

    // ---- Per-word prev/next tables (threads 0..44) ----
    if (rv && t < NWORDS) {
        const int fw = __ffsll((long long)B) - 1;
        const int firstv = (fw << 5) + __ffs(mask[fw]) - 1;
        const int lw = 63 - __clzll((long long)B);
        const int lastv  = (lw << 5) + 31 - __clz(mask[lw]);

        const unsigned long long lowB = B & ((1ull << t) - 1ull);
        int pv = lastv - NLON;                          // circular wrap
        if (lowB) {
            const int pw = 63 - __clzll((long long)lowB);
            pv = (pw << 5) + 31 - __clz(mask[pw]);
        }
        Ptab[t] = pv;

        const unsigned long long highB = B >> (t + 1);
        int nv = firstv + NLON;                         // circular wrap
        if (highB) {
            const int nw = (t + 1) + __ffsll((long long)highB) - 1;
            nv = (nw << 5) + __ffs(mask[nw]) - 1;
        }
        Ntab[t] = nv;
    }
    __syncthreads();

    // ---- Branch-free interpolation, 2 data-LDS per nibble ----
    if (rv) {
        const int bpos0 = (t & 7) << 2;                 // bit offset in word
        const unsigned lomask = (1u << bpos0) - 1u;

        #pragma unroll
        for (int k = 0; k < 3; k++) {
            if (k == 2 && !has2) break;
            const int vec   = t + k * NTH;
            const int i0    = vec << 2;
            const int w     = vec >> 3;
            const int wbase = w << 5;
            const unsigned cur = mask[w];
            const unsigned nib = (k == 0) ? nib0 : (k == 1) ? nib1 : nib2;
            const float4 r = (k == 0) ? r0 : (k == 1) ? r1 : r2;

            // Boundary prev: largest valid strictly below bpos0 (else Ptab).
            const unsigned lm = cur & lomask;
            const int prevB = lm ? (wbase + 31 - __clz(lm)) : Ptab[w];
            // Boundary next: smallest valid strictly above bpos0+3 (else Ntab).
            const unsigned long long hmbits = (unsigned long long)cur >> (bpos0 + 4);
            const int nextB = hmbits
                ? (wbase + bpos0 + 4 + __ffsll((long long)hmbits) - 1)
                : Ntab[w];

            // ONLY data loads for this nibble: the two boundary values.
            const float spB = sx[EIDX(prevB + NLON)];   // prevB+NLON in [0,2880)
            const float snB = sx[EIDX(nextB)];          // nextB      in [0,2880)

            // Index chains (1 SEL/element) + value chains (1 SEL/element).
            const int   p0 = (nib & 1u) ? (i0    ) : prevB;
            const int   p1 = (nib & 2u) ? (i0 + 1) : p0;
            const int   p2 = (nib & 4u) ? (i0 + 2) : p1;
            const int   p3 = (nib & 8u) ? (i0 + 3) : p2;
            const float q0 = (nib & 1u) ? r.x : spB;
            const float q1 = (nib & 2u) ? r.y : q0;
            const float q2 = (nib & 4u) ? r.z : q1;
            const float q3 = (nib & 8u) ? r.w : q2;

            const int   n3 = (nib & 8u) ? (i0 + 3) : nextB;
            const int   n2 = (nib & 4u) ? (i0 + 2) : n3;
            const int   n1 = (nib & 2u) ? (i0 + 1) : n2;
            const int   n0 = (nib & 1u) ? (i0    ) : n1;
            const float m3 = (nib & 8u) ? r.w : snB;
            const float m2 = (nib & 4u) ? r.z : m3;
            const float m1 = (nib & 2u) ? r.y : m2;
            const float m0 = (nib & 1u) ? r.x : m1;

            const int   P[4]  = {p0, p1, p2, p3};
            const int   N[4]  = {n0, n1, n2, n3};
            const float Q[4]  = {q0, q1, q2, q3};
            const float M[4]  = {m0, m1, m2, m3};
            const float RC[4] = {r.x, r.y, r.z, r.w};

            float res[4];
            #pragma unroll
            for (int c = 0; c < 4; c++) {
                // NaN element: P<i<N (dtot>=2). Valid element: discarded by SEL.
                const float tt = __fdividef((float)(i0 + c - P[c]),
                                            (float)(N[c] - P[c]));
                const float iv = fmaf(tt, M[c] - Q[c], Q[c]);
                res[c] = ((nib >> c) & 1u) ? RC[c] : iv;
            }
            dst[vec] = make_float4(res[0], res[1], res[2], res[3]);
        }
    } else {
        dst[t]       = r0;
        dst[t + 128] = r1;
        if (has2) dst[t + 256] = r2;
    }

    // ---- Last-CTA polar fill (ticket pattern; graph-capturable) ----
    __threadfence();
    __syncthreads();
    if (t == 0) {
        const int ticket = atomicAdd(&g_ticket, 1);
        s_is_last = (ticket == (int)gridDim.x - 1) ? 1 : 0;
    }
    __syncthreads();
    if (!s_is_last) return;

    for (int b = 0; b < NB; b++) {
        int lr = NLAT - 1;
        while (lr >= 0 && !g_row_valid[b * NLAT + lr]) lr--;
        if (lr < 0 || lr == NLAT - 1) continue;         // common case

        const float* __restrict__ fill = out + ((size_t)b * NLAT + lr) * NLON;
        for (int h = lr + 1; h < NLAT; h++) {
            const float* __restrict__ sr   = sst + ((size_t)b * NLAT + h) * NLON;
            float*       __restrict__ orow = out + ((size_t)b * NLAT + h) * NLON;
            for (int i = t; i < NLON; i += NTH) {
                if (nan_f(sr[i])) orow[i] = fill[i];
            }
        }
    }
    if (t == 0) g_ticket = 0;                           // reset for next replay
}

// ---------------------------------------------------------------------------
extern "C" void kernel_launch(void* const* d_in, const int* in_sizes, int n_in,
                              void* d_out, int out_size)
{
    const float* sst = (const float*)d_in[0];
    float*       out = (float*)d_out;

    fill_kernel<<<NROWS, NTH>>>((const float4*)sst, sst, out);
}

// round 8
// speedup vs baseline: 1.0819x; 1.0325x over previous
#include <cuda_runtime.h>
#include <cstdint>
#include <cstddef>

#define NB     32
#define NLAT   721
#define NLON   1440
#define NVEC   360          // NLON / 4
#define NWORDS 45           // NLON / 32
#define NTH    128
#define NROWS  (NB * NLAT)  // 23072

// Extended row: [0,1440) + duplicate [1440,2880), 16B-granular skew
// phys(j) = j + 4*(j>>5). Max phys = 2879 + 4*89 = 3235 -> pad to 3240.
#define EXTSZ  3240
#define EIDX(j) ((j) + (((j) >> 5) << 2))

// Cross-CTA scratch (no allocations allowed).
__device__ int g_row_valid[NROWS];
__device__ int g_ticket = 0;

__device__ __forceinline__ bool nan_f(float x) {
    return (__float_as_uint(x) & 0x7FFFFFFFu) > 0x7F800000u;
}

__device__ __forceinline__ unsigned combine8(unsigned v, int lane) {
    unsigned o = __shfl_xor_sync(0xFFFFFFFFu, v, 1);
    v = (lane & 1) ? ((v << 4) | o) : ((o << 4) | v);
    o = __shfl_xor_sync(0xFFFFFFFFu, v, 2);
    v = (lane & 2) ? ((v << 8) | o) : ((o << 8) | v);
    o = __shfl_xor_sync(0xFFFFFFFFu, v, 4);
    v = (lane & 4) ? ((v << 16) | o) : ((o << 16) | v);
    return v;
}

__device__ __forceinline__ unsigned nib_of(float4 r) {
    return (unsigned)(!nan_f(r.x))        | ((unsigned)(!nan_f(r.y)) << 1)
         | ((unsigned)(!nan_f(r.z)) << 2) | ((unsigned)(!nan_f(r.w)) << 3);
}

// ---------------------------------------------------------------------------
// Single fused kernel: one CTA per (b,lat) row; last CTA does the polar fill.
// Per nibble: ONE broadcast LDS.128 (mask,P,N) + TWO data LDS; float chains.
// ---------------------------------------------------------------------------
__global__ void __launch_bounds__(NTH)
fill_kernel(const float4* __restrict__ sst4, const float* __restrict__ sst,
            float* __restrict__ out)
{
    __shared__ float    sx[EXTSZ];      // skewed extended row
    __shared__ unsigned mask[NWORDS];   // used only while building wtab
    __shared__ int4     wtab[NWORDS];   // {mask, prevOutside, nextOutside, 0}
    __shared__ int      s_is_last;

    const int row  = blockIdx.x;        // b * NLAT + h
    const int t    = threadIdx.x;
    const int lane = t & 31;
    const bool has2 = (t < NVEC - 256); // t < 104

    const float4* __restrict__ src = sst4 + (size_t)row * NVEC;
    float4*       __restrict__ dst = (float4*)(out + (size_t)row * NLON);

    // ---- Front-batched loads (3 independent LDG.128) ----
    float4 r0 = src[t];
    float4 r1 = src[t + 128];
    float4 r2 = make_float4(0.f, 0.f, 0.f, 0.f);
    if (has2) r2 = src[t + 256];

    // ---- Store to skewed extended smem (float4 idx: vec + (vec>>3)) ----
    float4* sx4 = (float4*)sx;
    {
        const int v0 = t,            v0b = t + 360;
        const int v1 = t + 128,      v1b = t + 488;
        sx4[v0 + (v0 >> 3)]   = r0;  sx4[v0b + (v0b >> 3)] = r0;
        sx4[v1 + (v1 >> 3)]   = r1;  sx4[v1b + (v1b >> 3)] = r1;
        if (has2) {
            const int v2 = t + 256,  v2b = t + 616;
            sx4[v2 + (v2 >> 3)]   = r2;
            sx4[v2b + (v2b >> 3)] = r2;
        }
    }

    // ---- Validity nibbles + mask words via shuffles ----
    const unsigned nib0 = nib_of(r0);
    const unsigned nib1 = nib_of(r1);
    const unsigned nib2 = has2 ? nib_of(r2) : 0u;
    unsigned w0 = combine8(nib0, lane);
    unsigned w1 = combine8(nib1, lane);
    unsigned w2 = combine8(nib2, lane);
    if ((lane & 7) == 0) {
        const int widx = t >> 3;        // 0..15
        mask[widx]      = w0;
        mask[widx + 16] = w1;
        if (widx + 32 < NWORDS) mask[widx + 32] = w2;
    }
    __syncthreads();

    // ---- Word-validity bitmap B (redundant per warp: 2 ballots) ----
    const unsigned mwa = (lane < NWORDS)      ? mask[lane]      : 0u;
    const unsigned mwb = (lane + 32 < NWORDS) ? mask[lane + 32] : 0u;
    const unsigned b1 = __ballot_sync(0xFFFFFFFFu, mwa != 0u);
    const unsigned b2 = __ballot_sync(0xFFFFFFFFu, mwb != 0u);
    const unsigned long long B = ((unsigned long long)b2 << 32) | b1;
    const bool rv = (B != 0ull);

    if (t == 0) g_row_valid[row] = rv ? 1 : 0;

    // ---- Per-word packed table {mask, prev-outside, next-outside} ----
    if (rv && t < NWORDS) {
        const int fw = __ffsll((long long)B) - 1;
        const int firstv = (fw << 5) + __ffs(mask[fw]) - 1;
        const int lw = 63 - __clzll((long long)B);
        const int lastv  = (lw << 5) + 31 - __clz(mask[lw]);

        const unsigned long long lowB = B & ((1ull << t) - 1ull);
        int pv = lastv - NLON;                          // circular wrap
        if (lowB) {
            const int pw = 63 - __clzll((long long)lowB);
            pv = (pw << 5) + 31 - __clz(mask[pw]);
        }

        const unsigned long long highB = B >> (t + 1);
        int nv = firstv + NLON;                         // circular wrap
        if (highB) {
            const int nw = (t + 1) + __ffsll((long long)highB) - 1;
            nv = (nw << 5) + __ffs(mask[nw]) - 1;
        }
        wtab[t] = make_int4((int)mask[t], pv, nv, 0);
    }
    __syncthreads();

    // ---- Branch-free interpolation ----
    if (rv) {
        const int bpos0 = (t & 7) << 2;                 // bit offset in word
        const unsigned lomask = (1u << bpos0) - 1u;

        #pragma unroll
        for (int k = 0; k < 3; k++) {
            if (k == 2 && !has2) break;
            const int vec   = t + k * NTH;
            const int i0    = vec << 2;
            const int w     = vec >> 3;
            const int wbase = w << 5;
            const int4 wt   = wtab[w];                  // one LDS.128 (8-lane bcast)
            const unsigned cur = (unsigned)wt.x;
            const unsigned nib = (k == 0) ? nib0 : (k == 1) ? nib1 : nib2;
            const float4 r = (k == 0) ? r0 : (k == 1) ? r1 : r2;

            // Boundary prev: largest valid strictly below bpos0 (else wt.y).
            const unsigned lm = cur & lomask;
            const int prevB = lm ? (wbase + 31 - __clz(lm)) : wt.y;
            // Boundary next: smallest valid strictly above bpos0+3 (else wt.z).
            const unsigned hm = (cur >> (bpos0 + 3)) >> 1;
            const int nextB = hm ? (wbase + bpos0 + 3 + __ffs(hm)) : wt.z;

            // Only data loads for this nibble: the two boundary values.
            const float spB = sx[EIDX(prevB + NLON)];   // in [0, 2880)
            const float snB = sx[EIDX(nextB)];          // in [0, 2880)

            // Float index constants (exact: |idx| < 2^24).
            const float fi0 = (float)i0;
            const float fi1 = fi0 + 1.0f;
            const float fi2 = fi0 + 2.0f;
            const float fi3 = fi0 + 3.0f;
            const float fpB = (float)prevB;
            const float fnB = (float)nextB;

            // Index + value select chains (1 SEL/element each direction).
            const float fp0 = (nib & 1u) ? fi0 : fpB;
            const float fp1 = (nib & 2u) ? fi1 : fp0;
            const float fp2 = (nib & 4u) ? fi2 : fp1;
            const float fp3 = (nib & 8u) ? fi3 : fp2;
            const float q0  = (nib & 1u) ? r.x : spB;
            const float q1  = (nib & 2u) ? r.y : q0;
            const float q2  = (nib & 4u) ? r.z : q1;
            const float q3  = (nib & 8u) ? r.w : q2;

            const float fn3 = (nib & 8u) ? fi3 : fnB;
            const float fn2 = (nib & 4u) ? fi2 : fn3;
            const float fn1 = (nib & 2u) ? fi1 : fn2;
            const float fn0 = (nib & 1u) ? fi0 : fn1;
            const float m3  = (nib & 8u) ? r.w : snB;
            const float m2  = (nib & 4u) ? r.z : m3;
            const float m1  = (nib & 2u) ? r.y : m2;
            const float m0  = (nib & 1u) ? r.x : m1;

            const float FI[4] = {fi0, fi1, fi2, fi3};
            const float FP[4] = {fp0, fp1, fp2, fp3};
            const float FN[4] = {fn0, fn1, fn2, fn3};
            const float Q[4]  = {q0, q1, q2, q3};
            const float M[4]  = {m0, m1, m2, m3};
            const float RC[4] = {r.x, r.y, r.z, r.w};

            float res[4];
            #pragma unroll
            for (int c = 0; c < 4; c++) {
                // NaN element: FP<FI<FN (dt>=2, exact small ints in float).
                // Valid element: dt==0 -> inf/NaN -> discarded by the select.
                const float dp = FI[c] - FP[c];
                const float dt = FN[c] - FP[c];
                const float tt = __fdividef(dp, dt);
                const float iv = fmaf(tt, M[c] - Q[c], Q[c]);
                res[c] = ((nib >> c) & 1u) ? RC[c] : iv;
            }
            dst[vec] = make_float4(res[0], res[1], res[2], res[3]);
        }
    } else {
        dst[t]       = r0;
        dst[t + 128] = r1;
        if (has2) dst[t + 256] = r2;
    }

    // ---- Last-CTA polar fill (ticket pattern; graph-capturable) ----
    __threadfence();
    __syncthreads();
    if (t == 0) {
        const int ticket = atomicAdd(&g_ticket, 1);
        s_is_last = (ticket == (int)gridDim.x - 1) ? 1 : 0;
    }
    __syncthreads();
    if (!s_is_last) return;

    for (int b = 0; b < NB; b++) {
        int lr = NLAT - 1;
        while (lr >= 0 && !g_row_valid[b * NLAT + lr]) lr--;
        if (lr < 0 || lr == NLAT - 1) continue;         // common case

        const float* __restrict__ fill = out + ((size_t)b * NLAT + lr) * NLON;
        for (int h = lr + 1; h < NLAT; h++) {
            const float* __restrict__ sr   = sst + ((size_t)b * NLAT + h) * NLON;
            float*       __restrict__ orow = out + ((size_t)b * NLAT + h) * NLON;
            for (int i = t; i < NLON; i += NTH) {
                if (nan_f(sr[i])) orow[i] = fill[i];
            }
        }
    }
    if (t == 0) g_ticket = 0;                           // reset for next replay
}

// ---------------------------------------------------------------------------
extern "C" void kernel_launch(void* const* d_in, const int* in_sizes, int n_in,
                              void* d_out, int out_size)
{
    const float* sst = (const float*)d_in[0];
    float*       out = (float*)d_out;

    fill_kernel<<<NROWS, NTH>>>((const float4*)sst, sst, out);
}

// round 9
// speedup vs baseline: 1.1376x; 1.0515x over previous
#include <cuda_runtime.h>
#include <cstdint>
#include <cstddef>

#define NB     32
#define NLAT   721
#define NLON   1440
#define NVEC   360          // NLON / 4
#define NWORDS 45           // NLON / 32
#define NTH    128
#define NROWS  (NB * NLAT)  // 23072

// Extended row: [0,1440) + duplicate [1440,2880), 16B-granular skew
// phys(j) = j + 4*(j>>5). Max phys = 2879 + 4*89 = 3235 -> pad to 3240.
#define EXTSZ  3240
#define EIDX(j) ((j) + (((j) >> 5) << 2))

// Cross-CTA scratch (no allocations allowed).
__device__ int g_row_valid[NROWS];
__device__ int g_ticket = 0;

__device__ __forceinline__ bool nan_f(float x) {
    return (__float_as_uint(x) & 0x7FFFFFFFu) > 0x7F800000u;
}

__device__ __forceinline__ unsigned nib_of(float4 r) {
    return (unsigned)(!nan_f(r.x))        | ((unsigned)(!nan_f(r.y)) << 1)
         | ((unsigned)(!nan_f(r.z)) << 2) | ((unsigned)(!nan_f(r.w)) << 3);
}

// ---------------------------------------------------------------------------
// Single fused kernel: one CTA per (b,lat) row; last CTA does the polar fill.
// Mask build: per-thread nibble -> STS.U8, then 45 threads pack words
// (LDS.64 + 2 OR + PRMT) -- replaces the 18-SHFL butterfly entirely.
// ---------------------------------------------------------------------------
__global__ void __launch_bounds__(NTH)
fill_kernel(const float4* __restrict__ sst4, const float* __restrict__ sst,
            float* __restrict__ out)
{
    __shared__ float              sx[EXTSZ];       // skewed extended row
    __shared__ unsigned long long nibbuf64[NWORDS];// 360 nibble-bytes (8B aligned)
    __shared__ unsigned           mask[NWORDS];
    __shared__ int4               wtab[NWORDS];    // {mask, prevOutside, nextOutside, 0}
    __shared__ int                s_is_last;

    unsigned char* nibbuf = (unsigned char*)nibbuf64;

    const int row  = blockIdx.x;        // b * NLAT + h
    const int t    = threadIdx.x;
    const int lane = t & 31;
    const bool has2 = (t < NVEC - 256); // t < 104

    const float4* __restrict__ src = sst4 + (size_t)row * NVEC;
    float4*       __restrict__ dst = (float4*)(out + (size_t)row * NLON);

    // ---- Front-batched loads (3 independent LDG.128) ----
    float4 r0 = src[t];
    float4 r1 = src[t + 128];
    float4 r2 = make_float4(0.f, 0.f, 0.f, 0.f);
    if (has2) r2 = src[t + 256];

    // ---- Store to skewed extended smem (float4 idx: vec + (vec>>3)) ----
    float4* sx4 = (float4*)sx;
    {
        const int v0 = t,            v0b = t + 360;
        const int v1 = t + 128,      v1b = t + 488;
        sx4[v0 + (v0 >> 3)]   = r0;  sx4[v0b + (v0b >> 3)] = r0;
        sx4[v1 + (v1 >> 3)]   = r1;  sx4[v1b + (v1b >> 3)] = r1;
        if (has2) {
            const int v2 = t + 256,  v2b = t + 616;
            sx4[v2 + (v2 >> 3)]   = r2;
            sx4[v2b + (v2b >> 3)] = r2;
        }
    }

    // ---- Validity nibbles -> byte buffer (same-word byte STS merge) ----
    const unsigned nib0 = nib_of(r0);
    const unsigned nib1 = nib_of(r1);
    const unsigned nib2 = has2 ? nib_of(r2) : 0u;
    nibbuf[t]       = (unsigned char)nib0;
    nibbuf[t + 128] = (unsigned char)nib1;
    if (has2) nibbuf[t + 256] = (unsigned char)nib2;
    __syncthreads();

    // ---- Pack mask words: 8 nibble-bytes -> one 32-bit word ----
    if (t < NWORDS) {
        const uint2 b8 = ((const uint2*)nibbuf64)[t];
        const unsigned lo = b8.x | (b8.x >> 4);     // bytes0/2 = n0|n1<<4, n2|n3<<4
        const unsigned hi = b8.y | (b8.y >> 4);
        mask[t] = __byte_perm(lo, hi, 0x6420);
    }
    __syncthreads();

    // ---- Word-validity bitmap B (redundant per warp: 2 ballots) ----
    const unsigned mwa = (lane < NWORDS)      ? mask[lane]      : 0u;
    const unsigned mwb = (lane + 32 < NWORDS) ? mask[lane + 32] : 0u;
    const unsigned b1 = __ballot_sync(0xFFFFFFFFu, mwa != 0u);
    const unsigned b2 = __ballot_sync(0xFFFFFFFFu, mwb != 0u);
    const unsigned long long B = ((unsigned long long)b2 << 32) | b1;
    const bool rv = (B != 0ull);

    if (t == 0) g_row_valid[row] = rv ? 1 : 0;

    // ---- Per-word packed table {mask, prev-outside, next-outside} ----
    if (rv && t < NWORDS) {
        const int fw = __ffsll((long long)B) - 1;
        const int firstv = (fw << 5) + __ffs(mask[fw]) - 1;
        const int lw = 63 - __clzll((long long)B);
        const int lastv  = (lw << 5) + 31 - __clz(mask[lw]);

        const unsigned long long lowB = B & ((1ull << t) - 1ull);
        int pv = lastv - NLON;                          // circular wrap
        if (lowB) {
            const int pw = 63 - __clzll((long long)lowB);
            pv = (pw << 5) + 31 - __clz(mask[pw]);
        }

        const unsigned long long highB = B >> (t + 1);
        int nv = firstv + NLON;                         // circular wrap
        if (highB) {
            const int nw = (t + 1) + __ffsll((long long)highB) - 1;
            nv = (nw << 5) + __ffs(mask[nw]) - 1;
        }
        wtab[t] = make_int4((int)mask[t], pv, nv, 0);
    }
    __syncthreads();

    // ---- Branch-free interpolation ----
    if (rv) {
        const int bpos0 = (t & 7) << 2;                 // bit offset in word
        const unsigned lomask = (1u << bpos0) - 1u;

        #pragma unroll
        for (int k = 0; k < 3; k++) {
            if (k == 2 && !has2) break;
            const int vec   = t + k * NTH;
            const int i0    = vec << 2;
            const int w     = vec >> 3;
            const int wbase = w << 5;
            const int4 wt   = wtab[w];                  // one LDS.128 (8-lane bcast)
            const unsigned cur = (unsigned)wt.x;
            const unsigned nib = (k == 0) ? nib0 : (k == 1) ? nib1 : nib2;
            const float4 r = (k == 0) ? r0 : (k == 1) ? r1 : r2;

            // Boundary prev: largest valid strictly below bpos0 (else wt.y).
            const unsigned lm = cur & lomask;
            const int prevB = lm ? (wbase + 31 - __clz(lm)) : wt.y;
            // Boundary next: smallest valid strictly above bpos0+3 (else wt.z).
            const unsigned hm = (cur >> (bpos0 + 3)) >> 1;
            const int nextB = hm ? (wbase + bpos0 + 3 + __ffs(hm)) : wt.z;

            // Only data loads for this nibble: the two boundary values.
            const float spB = sx[EIDX(prevB + NLON)];   // in [0, 2880)
            const float snB = sx[EIDX(nextB)];          // in [0, 2880)

            // Float index constants (exact: |idx| < 2^24).
            const float fi0 = (float)i0;
            const float fi1 = fi0 + 1.0f;
            const float fi2 = fi0 + 2.0f;
            const float fi3 = fi0 + 3.0f;
            const float fpB = (float)prevB;
            const float fnB = (float)nextB;

            // Index + value select chains (1 SEL/element each direction).
            const float fp0 = (nib & 1u) ? fi0 : fpB;
            const float fp1 = (nib & 2u) ? fi1 : fp0;
            const float fp2 = (nib & 4u) ? fi2 : fp1;
            const float fp3 = (nib & 8u) ? fi3 : fp2;
            const float q0  = (nib & 1u) ? r.x : spB;
            const float q1  = (nib & 2u) ? r.y : q0;
            const float q2  = (nib & 4u) ? r.z : q1;
            const float q3  = (nib & 8u) ? r.w : q2;

            const float fn3 = (nib & 8u) ? fi3 : fnB;
            const float fn2 = (nib & 4u) ? fi2 : fn3;
            const float fn1 = (nib & 2u) ? fi1 : fn2;
            const float fn0 = (nib & 1u) ? fi0 : fn1;
            const float m3  = (nib & 8u) ? r.w : snB;
            const float m2  = (nib & 4u) ? r.z : m3;
            const float m1  = (nib & 2u) ? r.y : m2;
            const float m0  = (nib & 1u) ? r.x : m1;

            const float FI[4] = {fi0, fi1, fi2, fi3};
            const float FP[4] = {fp0, fp1, fp2, fp3};
            const float FN[4] = {fn0, fn1, fn2, fn3};
            const float Q[4]  = {q0, q1, q2, q3};
            const float M[4]  = {m0, m1, m2, m3};
            const float RC[4] = {r.x, r.y, r.z, r.w};

            float res[4];
            #pragma unroll
            for (int c = 0; c < 4; c++) {
                // NaN element: FP<FI<FN (dt>=2, exact small ints in float).
                // Valid element: dt==0 -> inf/NaN -> discarded by the select.
                const float dp = FI[c] - FP[c];
                const float dt = FN[c] - FP[c];
                const float tt = __fdividef(dp, dt);
                const float iv = fmaf(tt, M[c] - Q[c], Q[c]);
                res[c] = ((nib >> c) & 1u) ? RC[c] : iv;
            }
            dst[vec] = make_float4(res[0], res[1], res[2], res[3]);
        }
    } else {
        dst[t]       = r0;
        dst[t + 128] = r1;
        if (has2) dst[t + 256] = r2;
    }

    // ---- Last-CTA polar fill (ticket pattern; graph-capturable) ----
    __threadfence();
    __syncthreads();
    if (t == 0) {
        const int ticket = atomicAdd(&g_ticket, 1);
        s_is_last = (ticket == (int)gridDim.x - 1) ? 1 : 0;
    }
    __syncthreads();
    if (!s_is_last) return;

    for (int b = 0; b < NB; b++) {
        int lr = NLAT - 1;
        while (lr >= 0 && !g_row_valid[b * NLAT + lr]) lr--;
        if (lr < 0 || lr == NLAT - 1) continue;         // common case

        const float* __restrict__ fill = out + ((size_t)b * NLAT + lr) * NLON;
        for (int h = lr + 1; h < NLAT; h++) {
            const float* __restrict__ sr   = sst + ((size_t)b * NLAT + h) * NLON;
            float*       __restrict__ orow = out + ((size_t)b * NLAT + h) * NLON;
            for (int i = t; i < NLON; i += NTH) {
                if (nan_f(sr[i])) orow[i] = fill[i];
            }
        }
    }
    if (t == 0) g_ticket = 0;                           // reset for next replay
}

// ---------------------------------------------------------------------------
extern "C" void kernel_launch(void* const* d_in, const int* in_sizes, int n_in,
                              void* d_out, int out_size)
{
    const float* sst = (const float*)d_in[0];
    float*       out = (float*)d_out;

    fill_kernel<<<NROWS, NTH>>>((const float4*)sst, sst, out);
}

// round 10
// speedup vs baseline: 1.1714x; 1.0297x over previous
#include <cuda_runtime.h>
#include <cstdint>
#include <cstddef>

#define NB     32
#define NLAT   721
#define NLON   1440
#define NVEC   360          // NLON / 4
#define NWORDS 45           // NLON / 32
#define NUNITS 180          // NLON / 8 (one unit = one mask byte = 8 elements)
#define NTH    96
#define NROWS  (NB * NLAT)  // 23072

// Single skewed row copy: phys(j) = j + 4*(j>>5). Max 1439+4*44 = 1615.
#define SXSZ   1620
#define EIDX(j) ((j) + (((j) >> 5) << 2))

// Cross-CTA scratch (no allocations allowed).
__device__ int g_row_valid[NROWS];
__device__ int g_ticket = 0;

__device__ __forceinline__ bool nan_f(float x) {
    return (__float_as_uint(x) & 0x7FFFFFFFu) > 0x7F800000u;
}

__device__ __forceinline__ unsigned nib_of(float4 r) {
    return (unsigned)(!nan_f(r.x))        | ((unsigned)(!nan_f(r.y)) << 1)
         | ((unsigned)(!nan_f(r.z)) << 2) | ((unsigned)(!nan_f(r.w)) << 3);
}

// ---------------------------------------------------------------------------
// Per-unit (8 contiguous elements) branch-free interpolation.
// ---------------------------------------------------------------------------
struct RowCtx {
    const float* sx;
    const int4*  wtab;
};

__device__ __forceinline__ void do_unit(
    int u, unsigned byte8, float4 rA, float4 rB,
    const float* __restrict__ sx, const int4* __restrict__ wtab,
    float4* __restrict__ dst)
{
    const int w     = u >> 2;
    const int wbase = w << 5;
    const int bpos0 = (u & 3) << 3;                 // 0,8,16,24
    const int4 wt   = wtab[w];                      // one LDS.128 (4-lane bcast)
    const unsigned cur = (unsigned)wt.x;

    // Boundary prev: largest valid strictly below bpos0 (else wt.y).
    const unsigned lomask = (1u << bpos0) - 1u;     // bpos0=0 -> 0
    const unsigned lm = cur & lomask;
    const int prevB = lm ? (wbase + 31 - __clz(lm)) : wt.y;
    // Boundary next: smallest valid strictly above bpos0+7 (else wt.z).
    const unsigned hm = (cur >> (bpos0 + 7)) >> 1;
    const int nextB = hm ? (wbase + bpos0 + 7 + __ffs(hm)) : wt.z;

    // Wrap only for addressing (values); keep unwrapped for arithmetic.
    const int pmi = (prevB < 0)      ? prevB + NLON : prevB;
    const int nmi = (nextB >= NLON)  ? nextB - NLON : nextB;
    const float spB = sx[EIDX(pmi)];
    const float snB = sx[EIDX(nmi)];

    const float fi0 = (float)(u << 3);
    const float fpB = (float)prevB;
    const float fnB = (float)nextB;

    const float RC[8] = {rA.x, rA.y, rA.z, rA.w, rB.x, rB.y, rB.z, rB.w};

    // Ascending prev-index/value chains (1 SEL each per element).
    float FP[8], Q[8];
    {
        float fpc = fpB, qc = spB;
        #pragma unroll
        for (int c = 0; c < 8; c++) {
            const bool v = (byte8 >> c) & 1u;
            fpc = v ? (fi0 + (float)c) : fpc;
            qc  = v ? RC[c]            : qc;
            FP[c] = fpc; Q[c] = qc;
        }
    }
    // Descending next-index/value chains.
    float FN[8], M[8];
    {
        float fnc = fnB, mc = snB;
        #pragma unroll
        for (int c = 7; c >= 0; c--) {
            const bool v = (byte8 >> c) & 1u;
            fnc = v ? (fi0 + (float)c) : fnc;
            mc  = v ? RC[c]            : mc;
            FN[c] = fnc; M[c] = mc;
        }
    }

    float res[8];
    #pragma unroll
    for (int c = 0; c < 8; c++) {
        // NaN element: FP < FI < FN (dt >= 2, exact small ints in float).
        // Valid element: dt==0 -> 0*inf=NaN -> discarded by the select.
        const float fic = fi0 + (float)c;
        const float dp  = fic - FP[c];
        const float dt  = FN[c] - FP[c];
        const float tt  = __fdividef(dp, dt);
        const float iv  = fmaf(tt, M[c] - Q[c], Q[c]);
        res[c] = ((byte8 >> c) & 1u) ? RC[c] : iv;
    }
    dst[2 * u]     = make_float4(res[0], res[1], res[2], res[3]);
    dst[2 * u + 1] = make_float4(res[4], res[5], res[6], res[7]);
}

// ---------------------------------------------------------------------------
// Single fused kernel: one 96-thread CTA per (b,lat) row; last CTA polar-fills.
// Unit u (8 elems) <-> mask byte u: the nibble buffer IS the mask array.
// ---------------------------------------------------------------------------
__global__ void __launch_bounds__(NTH)
fill_kernel(const float4* __restrict__ sst4, const float* __restrict__ sst,
            float* __restrict__ out)
{
    __shared__ float    sx[SXSZ];       // skewed row (single copy)
    __shared__ unsigned mask[NWORDS];   // bytes written per-unit, read as words
    __shared__ int4     wtab[NWORDS];   // {mask, prevOutside, nextOutside, 0}
    __shared__ int      s_is_last;

    unsigned char* maskb = (unsigned char*)mask;

    const int row  = blockIdx.x;        // b * NLAT + h
    const int t    = threadIdx.x;
    const int lane = t & 31;
    const int u1   = t;                 // units 0..95
    const int u2   = t + NTH;           // units 96..179 (t < 84)
    const bool has2 = (t < NUNITS - NTH);

    const float4* __restrict__ src = sst4 + (size_t)row * NVEC;
    float4*       __restrict__ dst = (float4*)(out + (size_t)row * NLON);

    // ---- Front-batched loads (4 independent LDG.128) ----
    float4 a0 = src[2 * u1];
    float4 a1 = src[2 * u1 + 1];
    float4 b0 = make_float4(0.f, 0.f, 0.f, 0.f), b1 = b0;
    if (has2) { b0 = src[2 * u2]; b1 = src[2 * u2 + 1]; }

    // ---- Skewed smem store (float4 idx: v + (v>>3)) ----
    float4* sx4 = (float4*)sx;
    {
        const int v0 = 2 * u1, v1 = 2 * u1 + 1;
        sx4[v0 + (v0 >> 3)] = a0;
        sx4[v1 + (v1 >> 3)] = a1;
        if (has2) {
            const int v2 = 2 * u2, v3 = 2 * u2 + 1;
            sx4[v2 + (v2 >> 3)] = b0;
            sx4[v3 + (v3 >> 3)] = b1;
        }
    }

    // ---- Validity byte per unit -> mask bytes (no packing pass needed) ----
    const unsigned byteA = nib_of(a0) | (nib_of(a1) << 4);
    const unsigned byteB = has2 ? (nib_of(b0) | (nib_of(b1) << 4)) : 0u;
    maskb[u1] = (unsigned char)byteA;
    if (has2) maskb[u2] = (unsigned char)byteB;
    __syncthreads();

    // ---- Word-validity bitmap B (redundant per warp: 2 ballots) ----
    const unsigned mwa = (lane < NWORDS)      ? mask[lane]      : 0u;
    const unsigned mwb = (lane + 32 < NWORDS) ? mask[lane + 32] : 0u;
    const unsigned bb1 = __ballot_sync(0xFFFFFFFFu, mwa != 0u);
    const unsigned bb2 = __ballot_sync(0xFFFFFFFFu, mwb != 0u);
    const unsigned long long B = ((unsigned long long)bb2 << 32) | bb1;
    const bool rv = (B != 0ull);

    if (t == 0) g_row_valid[row] = rv ? 1 : 0;

    // ---- Per-word packed table {mask, prev-outside, next-outside} ----
    if (rv && t < NWORDS) {
        const int fw = __ffsll((long long)B) - 1;
        const int firstv = (fw << 5) + __ffs(mask[fw]) - 1;
        const int lw = 63 - __clzll((long long)B);
        const int lastv  = (lw << 5) + 31 - __clz(mask[lw]);

        const unsigned long long lowB = B & ((1ull << t) - 1ull);
        int pv = lastv - NLON;                          // circular wrap
        if (lowB) {
            const int pw = 63 - __clzll((long long)lowB);
            pv = (pw << 5) + 31 - __clz(mask[pw]);
        }

        const unsigned long long highB = B >> (t + 1);
        int nv = firstv + NLON;                         // circular wrap
        if (highB) {
            const int nw = (t + 1) + __ffsll((long long)highB) - 1;
            nv = (nw << 5) + __ffs(mask[nw]) - 1;
        }
        wtab[t] = make_int4((int)mask[t], pv, nv, 0);
    }
    __syncthreads();

    // ---- Branch-free interpolation (8 elements per unit) ----
    if (rv) {
        do_unit(u1, byteA, a0, a1, sx, wtab, dst);
        if (has2) do_unit(u2, byteB, b0, b1, sx, wtab, dst);
    } else {
        dst[2 * u1]     = a0;
        dst[2 * u1 + 1] = a1;
        if (has2) { dst[2 * u2] = b0; dst[2 * u2 + 1] = b1; }
    }

    // ---- Last-CTA polar fill (ticket pattern; graph-capturable) ----
    __threadfence();
    __syncthreads();
    if (t == 0) {
        const int ticket = atomicAdd(&g_ticket, 1);
        s_is_last = (ticket == (int)gridDim.x - 1) ? 1 : 0;
    }
    __syncthreads();
    if (!s_is_last) return;

    for (int b = 0; b < NB; b++) {
        int lr = NLAT - 1;
        while (lr >= 0 && !g_row_valid[b * NLAT + lr]) lr--;
        if (lr < 0 || lr == NLAT - 1) continue;         // common case

        const float* __restrict__ fill = out + ((size_t)b * NLAT + lr) * NLON;
        for (int h = lr + 1; h < NLAT; h++) {
            const float* __restrict__ sr   = sst + ((size_t)b * NLAT + h) * NLON;
            float*       __restrict__ orow = out + ((size_t)b * NLAT + h) * NLON;
            for (int i = t; i < NLON; i += NTH) {
                if (nan_f(sr[i])) orow[i] = fill[i];
            }
        }
    }
    if (t == 0) g_ticket = 0;                           // reset for next replay
}

// ---------------------------------------------------------------------------
extern "C" void kernel_launch(void* const* d_in, const int* in_sizes, int n_in,
                              void* d_out, int out_size)
{
    const float* sst = (const float*)d_in[0];
    float*       out = (float*)d_out;

    fill_kernel<<<NROWS, NTH>>>((const float4*)sst, sst, out);
}